// round 6
// baseline (speedup 1.0000x reference)
#include <cuda_runtime.h>
#include <math.h>

#define T_STEPS 1024
#define BATCH   64
#define DIM     256
#define NCTA    64

// ---- scratch (static __device__ arrays: allocation-free) ----
__device__ float g_Xz[T_STEPS * BATCH * DIM];
__device__ float g_Xr[T_STEPS * BATCH * DIM];
__device__ float g_Xh[T_STEPS * BATCH * DIM];
__device__ float g_h[BATCH * DIM];
__device__ float g_rh[BATCH * DIM];
__device__ unsigned g_flags[NCTA * 32];   // 128B-spaced per-CTA barrier flags

__global__ void reset_kernel() {
    for (int i = threadIdx.x; i < NCTA * 32; i += blockDim.x) g_flags[i] = 0u;
}

// ---- packed fp32x2 helpers (FFMA2: 2x fp32 FMA throughput, PTX-only) ----
__device__ __forceinline__ unsigned long long pack2(float lo, float hi) {
    unsigned long long r;
    asm("mov.b64 %0, {%1, %2};" : "=l"(r) : "f"(lo), "f"(hi));
    return r;
}
__device__ __forceinline__ float2 unpack2(unsigned long long v) {
    float lo, hi;
    asm("mov.b64 {%0, %1}, %2;" : "=f"(lo), "=f"(hi) : "l"(v));
    return make_float2(lo, hi);
}
__device__ __forceinline__ void ffma2(unsigned long long& d,
                                      unsigned long long a, unsigned long long b) {
    asm("fma.rn.f32x2 %0, %1, %2, %0;" : "+l"(d) : "l"(a), "l"(b));
}

// ============================================================
// Kernel A: X @ Wg + bg for g in {z, r, h}, fp32 via FFMA2.
// Output layout permuted for the recurrent kernel:
//   Xg[((t*64 + n/4)*64 + b)*4 + (n&3)]
// Block tile 64 rows (one t) x 64 cols, 256 threads, 4x4 per thread.
// ============================================================
__global__ __launch_bounds__(256) void x_proj_kernel(
    const float* __restrict__ X,
    const float* __restrict__ Wz, const float* __restrict__ Wr, const float* __restrict__ Wh,
    const float* __restrict__ bz, const float* __restrict__ br, const float* __restrict__ bh)
{
    const float* W; const float* bias; float* out;
    if (blockIdx.z == 0)      { W = Wz; bias = bz; out = g_Xz; }
    else if (blockIdx.z == 1) { W = Wr; bias = br; out = g_Xr; }
    else                      { W = Wh; bias = bh; out = g_Xh; }

    __shared__ __align__(16) float As[32][68];  // transposed X tile: As[k][row]
    __shared__ __align__(16) float Ws[32][68];  // W tile: Ws[k][col]

    const int tid = threadIdx.x;
    const int tx = tid & 15;          // 0..15 -> 4 cols each
    const int ty = tid >> 4;          // 0..15 -> 4 rows each
    const int t = blockIdx.x;
    const int col0 = blockIdx.y * 64;

    unsigned long long acc2[4][2];
#pragma unroll
    for (int i = 0; i < 4; i++) { acc2[i][0] = 0ull; acc2[i][1] = 0ull; }

    for (int kk = 0; kk < DIM; kk += 32) {
#pragma unroll
        for (int li = 0; li < 2; li++) {
            int idx = li * 256 + tid;          // 0..511
            int r = idx >> 3;                  // 0..63
            int q = idx & 7;
            float4 v = *(const float4*)&X[(t * 64 + r) * DIM + kk + q * 4];
            As[q * 4 + 0][r] = v.x;
            As[q * 4 + 1][r] = v.y;
            As[q * 4 + 2][r] = v.z;
            As[q * 4 + 3][r] = v.w;
        }
#pragma unroll
        for (int li = 0; li < 2; li++) {
            int idx = li * 256 + tid;
            int k = idx >> 4;
            int q = idx & 15;
            float4 v = *(const float4*)&W[(kk + k) * DIM + col0 + q * 4];
            *(float4*)&Ws[k][q * 4] = v;
        }
        __syncthreads();
#pragma unroll 8
        for (int k = 0; k < 32; k++) {
            float4 a = *(const float4*)&As[k][ty * 4];
            ulonglong2 w2 = *(const ulonglong2*)&Ws[k][tx * 4];
            unsigned long long d0 = pack2(a.x, a.x);
            unsigned long long d1 = pack2(a.y, a.y);
            unsigned long long d2 = pack2(a.z, a.z);
            unsigned long long d3 = pack2(a.w, a.w);
            ffma2(acc2[0][0], d0, w2.x); ffma2(acc2[0][1], d0, w2.y);
            ffma2(acc2[1][0], d1, w2.x); ffma2(acc2[1][1], d1, w2.y);
            ffma2(acc2[2][0], d2, w2.x); ffma2(acc2[2][1], d2, w2.y);
            ffma2(acc2[3][0], d3, w2.x); ffma2(acc2[3][1], d3, w2.y);
        }
        __syncthreads();
    }

    float4 bias4 = __ldg((const float4*)&bias[col0 + tx * 4]);
    const int nb = (col0 >> 2) + tx;
#pragma unroll
    for (int i = 0; i < 4; i++) {
        int bb = ty * 4 + i;
        float2 p0 = unpack2(acc2[i][0]);
        float2 p1 = unpack2(acc2[i][1]);
        float4 v = make_float4(p0.x + bias4.x, p0.y + bias4.y,
                               p1.x + bias4.z, p1.y + bias4.w);
        *(float4*)&out[((t * 64 + nb) * 64 + bb) * 4] = v;
    }
}

// ============================================================
// Kernel B: persistent recurrence. 64 CTAs x 256 threads.
// CTA cb owns output columns [cb*4, cb*4+4). Thread: b = tid>>2, nl = tid&3.
// Distributed-flag grid barrier: each CTA stores its own 128B-spaced flag;
// 64 threads poll the 64 flags in parallel (no contended atomics).
// All 64 CTAs are co-resident (1 CTA/SM at this smem size) -> deadlock-free.
// ============================================================
#define GRID_BARRIER()                                                   \
    do {                                                                 \
        __threadfence();                                                 \
        __syncthreads();                                                 \
        bars++;                                                          \
        if (tid == 0) *(volatile unsigned*)&g_flags[cb * 32] = bars;     \
        if (tid < NCTA) {                                                \
            while (*(volatile unsigned*)&g_flags[tid * 32] < bars) { }   \
        }                                                                \
        __syncthreads();                                                 \
    } while (0)

__global__ __launch_bounds__(256) void gru_rec_kernel(
    const float* __restrict__ Uh, const float* __restrict__ Ur,
    const float* __restrict__ Uz, const float* __restrict__ h0,
    float* __restrict__ out)
{
    extern __shared__ float smem[];
    float* hs = smem;                 // 64 rows x 260 (padded) floats
    float* us = smem + 64 * 260;      // U slices transposed: [z|r|h] x [4][256]

    const int tid = threadIdx.x;
    const int cb = blockIdx.x;        // 0..63
    const int b  = tid >> 2;          // 0..63
    const int nl = tid & 3;           // 0..3
    const int n  = cb * 4 + nl;

    // load this CTA's U column slices, transposed (us[g][nl][k] = Ug[k][n])
    for (int i = tid; i < 1024; i += 256) {
        int nn = i >> 8, k = i & 255;
        int gcol = cb * 4 + nn;
        us[i]        = __ldg(&Uz[k * DIM + gcol]);
        us[1024 + i] = __ldg(&Ur[k * DIM + gcol]);
        us[2048 + i] = __ldg(&Uh[k * DIM + gcol]);
    }

    float h_own = __ldg(&h0[n]);      // init_hidden broadcast over batch
    g_h[b * DIM + n] = h_own;

    unsigned bars = 0;
    GRID_BARRIER();                   // init h visible everywhere; us loaded

    const ulonglong2* hrowp = (const ulonglong2*)(hs + b * 260);  // 64 u64x2/row
    const ulonglong2* uzp   = (const ulonglong2*)(us + nl * 256);
    const ulonglong2* urp   = (const ulonglong2*)(us + 1024 + nl * 256);
    const ulonglong2* uhp   = (const ulonglong2*)(us + 2048 + nl * 256);
    const float4* gh4  = (const float4*)g_h;
    const float4* grh4 = (const float4*)g_rh;

    for (int t = 0; t < T_STEPS; t++) {
        // prefetch this step's x-projection values (coalesced 128B/warp)
        int xidx = ((t * 64 + cb) * 64 + b) * 4 + nl;
        float xz = __ldg(&g_Xz[xidx]);
        float xr = __ldg(&g_Xr[xidx]);
        float xh = __ldg(&g_Xh[xidx]);

        // emit PRE-update hidden (reference semantics)
        out[(t * BATCH + b) * DIM + n] = h_own;

        // ---- phase 1: load full h into smem, compute z & r for own cols ----
#pragma unroll
        for (int i = 0; i < 16; i++) {
            int idx = i * 256 + tid;            // 0..4095 float4s
            int r = idx >> 6, c = idx & 63;
            float4 v = __ldcg(gh4 + idx);
            *((float4*)(hs + r * 260) + c) = v;
        }
        __syncthreads();

        unsigned long long az0 = pack2(xz, 0.0f), az1 = 0ull;
        unsigned long long ar0 = pack2(xr, 0.0f), ar1 = 0ull;
#pragma unroll 8
        for (int k4 = 0; k4 < 64; k4++) {
            ulonglong2 hv = hrowp[k4];
            ulonglong2 a  = uzp[k4];
            ulonglong2 c  = urp[k4];
            ffma2(az0, hv.x, a.x); ffma2(az1, hv.y, a.y);
            ffma2(ar0, hv.x, c.x); ffma2(ar1, hv.y, c.y);
        }
        float2 za = unpack2(az0), zb = unpack2(az1);
        float2 ra = unpack2(ar0), rb = unpack2(ar1);
        float az = (za.x + za.y) + (zb.x + zb.y);
        float ar = (ra.x + ra.y) + (rb.x + rb.y);
        float z = 1.0f / (1.0f + __expf(-az));
        float r = 1.0f / (1.0f + __expf(-ar));
        g_rh[b * DIM + n] = r * h_own;
        GRID_BARRIER();

        // ---- phase 2: load full r*h, compute h_bar, combine ----
#pragma unroll
        for (int i = 0; i < 16; i++) {
            int idx = i * 256 + tid;
            int rr = idx >> 6, c = idx & 63;
            float4 v = __ldcg(grh4 + idx);
            *((float4*)(hs + rr * 260) + c) = v;
        }
        __syncthreads();

        unsigned long long ah0 = pack2(xh, 0.0f), ah1 = 0ull;
#pragma unroll 8
        for (int k4 = 0; k4 < 64; k4++) {
            ulonglong2 hv = hrowp[k4];
            ulonglong2 a  = uhp[k4];
            ffma2(ah0, hv.x, a.x); ffma2(ah1, hv.y, a.y);
        }
        float2 ha = unpack2(ah0), hb = unpack2(ah1);
        float ah = (ha.x + ha.y) + (hb.x + hb.y);
        ah = fminf(fmaxf(ah, -20.0f), 20.0f);     // avoid inf/inf -> NaN
        float e = __expf(-2.0f * ah);
        float hbar = (1.0f - e) / (1.0f + e);     // tanh(ah)

        float hnew = (1.0f - r) * h_own + z * hbar;   // (1-r) per reference
        h_own = hnew;
        g_h[b * DIM + n] = hnew;
        GRID_BARRIER();
    }
}

extern "C" void kernel_launch(void* const* d_in, const int* in_sizes, int n_in,
                              void* d_out, int out_size)
{
    const float* X   = (const float*)d_in[0];
    const float* W   = (const float*)d_in[1];
    const float* U   = (const float*)d_in[2];
    const float* bh  = (const float*)d_in[3];
    const float* W_r = (const float*)d_in[4];
    const float* U_r = (const float*)d_in[5];
    const float* b_r = (const float*)d_in[6];
    const float* W_z = (const float*)d_in[7];
    const float* U_z = (const float*)d_in[8];
    const float* b_z = (const float*)d_in[9];
    const float* h0  = (const float*)d_in[10];
    float* out = (float*)d_out;

    const int rec_smem = (64 * 260 + 3 * 1024) * (int)sizeof(float);  // 78848 B
    cudaFuncSetAttribute(gru_rec_kernel,
                         cudaFuncAttributeMaxDynamicSharedMemorySize, rec_smem);

    reset_kernel<<<1, 256>>>();
    x_proj_kernel<<<dim3(T_STEPS, 4, 3), 256>>>(X, W_z, W_r, W, b_z, b_r, bh);
    gru_rec_kernel<<<NCTA, 256, rec_smem>>>(U, U_r, U_z, h0, out);
}

// round 7
// speedup vs baseline: 2.3958x; 2.3958x over previous
#include <cuda_runtime.h>
#include <math.h>

#define T_STEPS 1024
#define BATCH   64
#define DIM     256
#define NCTA    64
#define KCHUNK  32            // k values per lane: k = kidx*8 + kq

// ---- scratch (static __device__ arrays: allocation-free) ----
__device__ float g_Xz[T_STEPS * BATCH * DIM];   // ((t*64+cb)*64 + b)*4 + nl
__device__ float g_Xr[T_STEPS * BATCH * DIM];
__device__ float g_Xh[T_STEPS * BATCH * DIM];
__device__ float g_h [DIM * BATCH];             // transposed: [n][b]
__device__ float g_rh[DIM * BATCH];             // transposed: [n][b]
__device__ unsigned g_flags[NCTA * 32];         // 128B-spaced per-CTA flags

// ---- packed fp32x2 helpers (FFMA2: 2x fp32 FMA throughput, PTX-only) ----
__device__ __forceinline__ unsigned long long pack2(float lo, float hi) {
    unsigned long long r;
    asm("mov.b64 %0, {%1, %2};" : "=l"(r) : "f"(lo), "f"(hi));
    return r;
}
__device__ __forceinline__ float2 unpack2(unsigned long long v) {
    float lo, hi;
    asm("mov.b64 {%0, %1}, %2;" : "=f"(lo), "=f"(hi) : "l"(v));
    return make_float2(lo, hi);
}
__device__ __forceinline__ void ffma2(unsigned long long& d,
                                      unsigned long long a, unsigned long long b) {
    asm("fma.rn.f32x2 %0, %1, %2, %0;" : "+l"(d) : "l"(a), "l"(b));
}
__device__ __forceinline__ unsigned long long addf2(unsigned long long a,
                                                    unsigned long long b) {
    unsigned long long r;
    asm("add.rn.f32x2 %0, %1, %2;" : "=l"(r) : "l"(a), "l"(b));
    return r;
}

// extract element i (0..7) from 4 packed f32x2 (pair j holds elems 2j, 2j+1)
__device__ __forceinline__ float extract8(const unsigned long long* a, int i) {
    float2 p0 = unpack2(a[0]), p1 = unpack2(a[1]);
    float2 p2 = unpack2(a[2]), p3 = unpack2(a[3]);
    float e0 = (i & 1) ? p0.y : p0.x;
    float e1 = (i & 1) ? p1.y : p1.x;
    float e2 = (i & 1) ? p2.y : p2.x;
    float e3 = (i & 1) ? p3.y : p3.x;
    float f0 = (i & 2) ? e1 : e0;
    float f1 = (i & 2) ? e3 : e2;
    return (i & 4) ? f1 : f0;
}

// ============================================================
// Kernel A: X @ Wg + bg for g in {z, r, h}, fp32 via FFMA2.
// Also resets the grid-barrier flags (block (0,0,0)).
// Output layout: Xg[((t*64 + n/4)*64 + b)*4 + (n&3)]
// ============================================================
__global__ __launch_bounds__(256) void x_proj_kernel(
    const float* __restrict__ X,
    const float* __restrict__ Wz, const float* __restrict__ Wr, const float* __restrict__ Wh,
    const float* __restrict__ bz, const float* __restrict__ br, const float* __restrict__ bh)
{
    const int tid = threadIdx.x;
    if (blockIdx.x == 0 && blockIdx.y == 0 && blockIdx.z == 0 && tid < NCTA)
        g_flags[tid * 32] = 0u;    // stream-ordered before the rec kernel

    const float* W; const float* bias; float* out;
    if (blockIdx.z == 0)      { W = Wz; bias = bz; out = g_Xz; }
    else if (blockIdx.z == 1) { W = Wr; bias = br; out = g_Xr; }
    else                      { W = Wh; bias = bh; out = g_Xh; }

    __shared__ __align__(16) float As[32][68];  // transposed X tile: As[k][row]
    __shared__ __align__(16) float Ws[32][68];  // W tile: Ws[k][col]

    const int tx = tid & 15;
    const int ty = tid >> 4;
    const int t = blockIdx.x;
    const int col0 = blockIdx.y * 64;

    unsigned long long acc2[4][2];
#pragma unroll
    for (int i = 0; i < 4; i++) { acc2[i][0] = 0ull; acc2[i][1] = 0ull; }

    for (int kk = 0; kk < DIM; kk += 32) {
#pragma unroll
        for (int li = 0; li < 2; li++) {
            int idx = li * 256 + tid;
            int r = idx >> 3;
            int q = idx & 7;
            float4 v = *(const float4*)&X[(t * 64 + r) * DIM + kk + q * 4];
            As[q * 4 + 0][r] = v.x;
            As[q * 4 + 1][r] = v.y;
            As[q * 4 + 2][r] = v.z;
            As[q * 4 + 3][r] = v.w;
        }
#pragma unroll
        for (int li = 0; li < 2; li++) {
            int idx = li * 256 + tid;
            int k = idx >> 4;
            int q = idx & 15;
            float4 v = *(const float4*)&W[(kk + k) * DIM + col0 + q * 4];
            *(float4*)&Ws[k][q * 4] = v;
        }
        __syncthreads();
#pragma unroll 8
        for (int k = 0; k < 32; k++) {
            float4 a = *(const float4*)&As[k][ty * 4];
            ulonglong2 w2 = *(const ulonglong2*)&Ws[k][tx * 4];
            unsigned long long d0 = pack2(a.x, a.x);
            unsigned long long d1 = pack2(a.y, a.y);
            unsigned long long d2 = pack2(a.z, a.z);
            unsigned long long d3 = pack2(a.w, a.w);
            ffma2(acc2[0][0], d0, w2.x); ffma2(acc2[0][1], d0, w2.y);
            ffma2(acc2[1][0], d1, w2.x); ffma2(acc2[1][1], d1, w2.y);
            ffma2(acc2[2][0], d2, w2.x); ffma2(acc2[2][1], d2, w2.y);
            ffma2(acc2[3][0], d3, w2.x); ffma2(acc2[3][1], d3, w2.y);
        }
        __syncthreads();
    }

    float4 bias4 = __ldg((const float4*)&bias[col0 + tx * 4]);
    const int nb = (col0 >> 2) + tx;
#pragma unroll
    for (int i = 0; i < 4; i++) {
        int bb = ty * 4 + i;
        float2 p0 = unpack2(acc2[i][0]);
        float2 p1 = unpack2(acc2[i][1]);
        float4 v = make_float4(p0.x + bias4.x, p0.y + bias4.y,
                               p1.x + bias4.z, p1.y + bias4.w);
        *(float4*)&out[((t * 64 + nb) * 64 + bb) * 4] = v;
    }
}

// ============================================================
// Kernel B: persistent recurrence. 64 CTAs x 256 threads (8 warps).
// CTA cb owns cols n = cb*4 .. cb*4+3.
// Warp w owns batches b = 8w .. 8w+7. Lane l: nl = l&3, kq = l>>2.
// Lane's scalar identity: (b = 8w+kq, n = cb*4+nl).
// U held in REGISTERS (loop-invariant, fully unrolled k-loop).
// h exchanged transposed [n][b]; smem hs[k][b] stride 68 (bank-clean).
// Per k: 2 LDS.128 (8 h, 4-way lane-broadcast) -> 8 FFMA2 (16 MACs).
// Split-k 8-way over kq lanes (k = kidx*8+kq), reduced via shfl.xor.
// ============================================================
#define GRID_BARRIER()                                                   \
    do {                                                                 \
        __threadfence();                                                 \
        __syncthreads();                                                 \
        bars++;                                                          \
        if (tid == 0) *(volatile unsigned*)&g_flags[cb * 32] = bars;     \
        if (tid < NCTA) {                                                \
            while (*(volatile unsigned*)&g_flags[tid * 32] < bars) { }   \
        }                                                                \
        __syncthreads();                                                 \
    } while (0)

__global__ __launch_bounds__(256) void gru_rec_kernel(
    const float* __restrict__ Uh, const float* __restrict__ Ur,
    const float* __restrict__ Uz, const float* __restrict__ h0,
    float* __restrict__ out)
{
    extern __shared__ float hs[];   // [256][68] floats = 69632 B

    const int tid = threadIdx.x;
    const int cb = blockIdx.x;
    const int w  = tid >> 5;       // warp 0..7 -> b-group
    const int l  = tid & 31;
    const int nl = l & 3;          // column within CTA
    const int kq = l >> 2;         // split-k lane 0..7
    const int n  = cb * 4 + nl;
    const int b  = w * 8 + kq;

    // ---- loop-invariant U slices into registers ----
    float uzr[KCHUNK], urr[KCHUNK], uhr[KCHUNK];
#pragma unroll
    for (int i = 0; i < KCHUNK; i++) {
        int k = i * 8 + kq;
        uzr[i] = __ldg(&Uz[k * DIM + n]);
        urr[i] = __ldg(&Ur[k * DIM + n]);
        uhr[i] = __ldg(&Uh[k * DIM + n]);
    }

    float h_mine = __ldg(&h0[n]);      // init hidden, broadcast over batch
    g_h[n * BATCH + b] = h_mine;

    unsigned bars = 0;
    GRID_BARRIER();                    // init h visible; flags synced

    const float4* gh4  = (const float4*)g_h;
    const float4* grh4 = (const float4*)g_rh;
    const float*  hbase = &hs[kq * 68 + w * 8];

    for (int t = 0; t < T_STEPS; t++) {
        // this step's x projections (coalesced: addr = base + lane)
        int xidx = ((t * 64 + cb) * 64 + b) * 4 + nl;
        float xz = __ldg(&g_Xz[xidx]);
        float xr = __ldg(&g_Xr[xidx]);
        float xh = __ldg(&g_Xh[xidx]);

        // emit PRE-update hidden (reference semantics)
        out[(t * BATCH + b) * DIM + n] = h_mine;

        // ---- phase 1: stage h (transposed) into smem ----
#pragma unroll
        for (int i = 0; i < 16; i++) {
            int idx = i * 256 + tid;          // float4 index, 0..4095
            int r = idx >> 4, c = idx & 15;
            float4 v = __ldcg(gh4 + idx);
            *(float4*)&hs[r * 68 + c * 4] = v;
        }
        __syncthreads();

        unsigned long long az[4] = {0,0,0,0}, ar[4] = {0,0,0,0};
#pragma unroll
        for (int i = 0; i < KCHUNK; i++) {
            const float* hp = hbase + i * (8 * 68);
            ulonglong2 h01 = *(const ulonglong2*)(hp);       // b0..b3
            ulonglong2 h23 = *(const ulonglong2*)(hp + 4);   // b4..b7
            unsigned long long uz2 = pack2(uzr[i], uzr[i]);
            unsigned long long ur2 = pack2(urr[i], urr[i]);
            ffma2(az[0], h01.x, uz2); ffma2(az[1], h01.y, uz2);
            ffma2(az[2], h23.x, uz2); ffma2(az[3], h23.y, uz2);
            ffma2(ar[0], h01.x, ur2); ffma2(ar[1], h01.y, ur2);
            ffma2(ar[2], h23.x, ur2); ffma2(ar[3], h23.y, ur2);
        }
        // reduce over the 8 kq lanes (stride-4 butterfly)
#pragma unroll
        for (int m = 4; m <= 16; m <<= 1) {
#pragma unroll
            for (int j = 0; j < 4; j++) {
                az[j] = addf2(az[j], __shfl_xor_sync(0xffffffffu, az[j], m));
                ar[j] = addf2(ar[j], __shfl_xor_sync(0xffffffffu, ar[j], m));
            }
        }
        float azm = extract8(az, kq) + xz;
        float arm = extract8(ar, kq) + xr;
        float z = 1.0f / (1.0f + __expf(-azm));
        float r = 1.0f / (1.0f + __expf(-arm));
        g_rh[n * BATCH + b] = r * h_mine;
        GRID_BARRIER();

        // ---- phase 2: stage r*h, compute h_bar, combine ----
#pragma unroll
        for (int i = 0; i < 16; i++) {
            int idx = i * 256 + tid;
            int rr = idx >> 4, c = idx & 15;
            float4 v = __ldcg(grh4 + idx);
            *(float4*)&hs[rr * 68 + c * 4] = v;
        }
        __syncthreads();

        unsigned long long ah[4] = {0,0,0,0};
#pragma unroll
        for (int i = 0; i < KCHUNK; i++) {
            const float* hp = hbase + i * (8 * 68);
            ulonglong2 h01 = *(const ulonglong2*)(hp);
            ulonglong2 h23 = *(const ulonglong2*)(hp + 4);
            unsigned long long uh2 = pack2(uhr[i], uhr[i]);
            ffma2(ah[0], h01.x, uh2); ffma2(ah[1], h01.y, uh2);
            ffma2(ah[2], h23.x, uh2); ffma2(ah[3], h23.y, uh2);
        }
#pragma unroll
        for (int m = 4; m <= 16; m <<= 1) {
#pragma unroll
            for (int j = 0; j < 4; j++)
                ah[j] = addf2(ah[j], __shfl_xor_sync(0xffffffffu, ah[j], m));
        }
        float ahm = extract8(ah, kq) + xh;
        ahm = fminf(fmaxf(ahm, -20.0f), 20.0f);
        float e = __expf(-2.0f * ahm);
        float hbar = (1.0f - e) / (1.0f + e);     // tanh

        float hnew = (1.0f - r) * h_mine + z * hbar;   // (1-r) per reference
        h_mine = hnew;
        g_h[n * BATCH + b] = hnew;
        GRID_BARRIER();
    }
}

extern "C" void kernel_launch(void* const* d_in, const int* in_sizes, int n_in,
                              void* d_out, int out_size)
{
    const float* X   = (const float*)d_in[0];
    const float* W   = (const float*)d_in[1];
    const float* U   = (const float*)d_in[2];
    const float* bh  = (const float*)d_in[3];
    const float* W_r = (const float*)d_in[4];
    const float* U_r = (const float*)d_in[5];
    const float* b_r = (const float*)d_in[6];
    const float* W_z = (const float*)d_in[7];
    const float* U_z = (const float*)d_in[8];
    const float* b_z = (const float*)d_in[9];
    const float* h0  = (const float*)d_in[10];
    float* out = (float*)d_out;

    const int rec_smem = 256 * 68 * (int)sizeof(float);   // 69632 B
    cudaFuncSetAttribute(gru_rec_kernel,
                         cudaFuncAttributeMaxDynamicSharedMemorySize, rec_smem);

    x_proj_kernel<<<dim3(T_STEPS, 4, 3), 256>>>(X, W_z, W_r, W, b_z, b_r, bh);
    gru_rec_kernel<<<NCTA, 256, rec_smem>>>(U, U_r, U_z, h0, out);
}

// round 8
// speedup vs baseline: 3.6626x; 1.5287x over previous
#include <cuda_runtime.h>
#include <math.h>

#define T_STEPS 1024
#define BATCH   64
#define DIM     256
#define NB      16              // batch groups (independent sync rows)
#define BPG     4               // batches per group
#define NN      8               // column groups per row
#define NPG     32              // columns per CTA
#define NCTA    (NB * NN)       // 128 CTAs (< 148 SMs -> all co-resident)
#define KPW     32              // k-range per warp (8 warps cover DIM=256)

// ---- scratch (static __device__ arrays: allocation-free) ----
__device__ float g_Xz[T_STEPS * BATCH * DIM];   // [((t*8+ng)*16+bg)*128 + bl*32 + nl]
__device__ float g_Xr[T_STEPS * BATCH * DIM];
__device__ float g_Xh[T_STEPS * BATCH * DIM];
__device__ float g_h [NB * DIM * BPG];          // [bg][k][bl]
__device__ float g_rh[NB * DIM * BPG];          // [bg][k][bl]
__device__ unsigned g_flags[NCTA * 32];         // 128B-spaced flags, [bg*8+ng]

// ---- packed fp32x2 helpers (PTX-only f32x2 ops: 2x fp32 throughput) ----
__device__ __forceinline__ unsigned long long pack2(float lo, float hi) {
    unsigned long long r;
    asm("mov.b64 %0, {%1, %2};" : "=l"(r) : "f"(lo), "f"(hi));
    return r;
}
__device__ __forceinline__ float2 unpack2(unsigned long long v) {
    float lo, hi;
    asm("mov.b64 {%0, %1}, %2;" : "=f"(lo), "=f"(hi) : "l"(v));
    return make_float2(lo, hi);
}
__device__ __forceinline__ void ffma2(unsigned long long& d,
                                      unsigned long long a, unsigned long long b) {
    asm("fma.rn.f32x2 %0, %1, %2, %0;" : "+l"(d) : "l"(a), "l"(b));
}
__device__ __forceinline__ unsigned long long addf2(unsigned long long a,
                                                    unsigned long long b) {
    unsigned long long r;
    asm("add.rn.f32x2 %0, %1, %2;" : "=l"(r) : "l"(a), "l"(b));
    return r;
}
__device__ __forceinline__ float sigmoidf_(float x) {
    return 1.0f / (1.0f + __expf(-x));
}
__device__ __forceinline__ float tanh_clamped(float x) {
    x = fminf(fmaxf(x, -20.0f), 20.0f);
    float e = __expf(-2.0f * x);
    return (1.0f - e) / (1.0f + e);
}

// ============================================================
// Kernel A: X @ Wg + bg for g in {z, r, h} (fp32, FFMA2).
// Block (0,0,0) also resets the barrier flags (stream-ordered).
// Output layout: Xg[((t*8 + n/32)*16 + b/4)*128 + (b%4)*32 + (n%32)]
// ============================================================
__global__ __launch_bounds__(256) void x_proj_kernel(
    const float* __restrict__ X,
    const float* __restrict__ Wz, const float* __restrict__ Wr, const float* __restrict__ Wh,
    const float* __restrict__ bz, const float* __restrict__ br, const float* __restrict__ bh)
{
    const int tid = threadIdx.x;
    if (blockIdx.x == 0 && blockIdx.y == 0 && blockIdx.z == 0 && tid < NCTA)
        g_flags[tid * 32] = 0u;

    const float* W; const float* bias; float* out;
    if (blockIdx.z == 0)      { W = Wz; bias = bz; out = g_Xz; }
    else if (blockIdx.z == 1) { W = Wr; bias = br; out = g_Xr; }
    else                      { W = Wh; bias = bh; out = g_Xh; }

    __shared__ __align__(16) float As[32][68];  // transposed X tile: As[k][row]
    __shared__ __align__(16) float Ws[32][68];  // W tile: Ws[k][col]

    const int tx = tid & 15;          // 4 cols each
    const int ty = tid >> 4;          // 4 rows each (rows = batch)
    const int t = blockIdx.x;
    const int col0 = blockIdx.y * 64;

    unsigned long long acc2[4][2];
#pragma unroll
    for (int i = 0; i < 4; i++) { acc2[i][0] = 0ull; acc2[i][1] = 0ull; }

    for (int kk = 0; kk < DIM; kk += 32) {
#pragma unroll
        for (int li = 0; li < 2; li++) {
            int idx = li * 256 + tid;
            int r = idx >> 3;
            int q = idx & 7;
            float4 v = *(const float4*)&X[(t * 64 + r) * DIM + kk + q * 4];
            As[q * 4 + 0][r] = v.x;
            As[q * 4 + 1][r] = v.y;
            As[q * 4 + 2][r] = v.z;
            As[q * 4 + 3][r] = v.w;
        }
#pragma unroll
        for (int li = 0; li < 2; li++) {
            int idx = li * 256 + tid;
            int k = idx >> 4;
            int q = idx & 15;
            float4 v = *(const float4*)&W[(kk + k) * DIM + col0 + q * 4];
            *(float4*)&Ws[k][q * 4] = v;
        }
        __syncthreads();
#pragma unroll 8
        for (int k = 0; k < 32; k++) {
            float4 a = *(const float4*)&As[k][ty * 4];
            ulonglong2 w2 = *(const ulonglong2*)&Ws[k][tx * 4];
            unsigned long long d0 = pack2(a.x, a.x);
            unsigned long long d1 = pack2(a.y, a.y);
            unsigned long long d2 = pack2(a.z, a.z);
            unsigned long long d3 = pack2(a.w, a.w);
            ffma2(acc2[0][0], d0, w2.x); ffma2(acc2[0][1], d0, w2.y);
            ffma2(acc2[1][0], d1, w2.x); ffma2(acc2[1][1], d1, w2.y);
            ffma2(acc2[2][0], d2, w2.x); ffma2(acc2[2][1], d2, w2.y);
            ffma2(acc2[3][0], d3, w2.x); ffma2(acc2[3][1], d3, w2.y);
        }
        __syncthreads();
    }

    float4 bias4 = __ldg((const float4*)&bias[col0 + tx * 4]);
    // new layout: bg = ty, bl = i, ng = (col0 + tx*4)/32, nl = (tx&7)*4 + j
    const int ngx = blockIdx.y * 2 + (tx >> 3);
    const int nl0 = (tx & 7) * 4;
#pragma unroll
    for (int i = 0; i < 4; i++) {
        float2 p0 = unpack2(acc2[i][0]);
        float2 p1 = unpack2(acc2[i][1]);
        float4 v = make_float4(p0.x + bias4.x, p0.y + bias4.y,
                               p1.x + bias4.z, p1.y + bias4.w);
        *(float4*)&out[((t * NN + ngx) * NB + ty) * 128 + i * 32 + nl0] = v;
    }
}

// ============================================================
// Kernel B: persistent recurrence, 128 CTAs x 256 threads.
// CTA (bg, ng) owns batches [bg*4, bg*4+4) x columns [ng*32, ng*32+32).
// 16 rows (bg) are fully independent; each row of 8 CTAs syncs via its
// own 8 flags. Warp w handles k in [w*32, w*32+32) (broadcast LDS.128 of
// staged h[k][0..3]); per-warp partials reduced via one smem round-trip.
// 64 "owner" threads (tid<64: n=tid&31, bpair=tid>>5) keep z, r, h in
// registers across both phases.
// ============================================================
#define ROW_BARRIER()                                                       \
    do {                                                                    \
        __syncthreads();                                                    \
        bars++;                                                             \
        if (tid == 0)                                                       \
            *(volatile unsigned*)&g_flags[(bg * NN + ng) * 32] = bars;      \
        if (tid < NN) {                                                     \
            while (*(volatile unsigned*)&g_flags[(bg * NN + tid) * 32] < bars) { } \
        }                                                                   \
        __syncthreads();                                                    \
    } while (0)

__global__ __launch_bounds__(256) void gru_rec_kernel(
    const float* __restrict__ Uh, const float* __restrict__ Ur,
    const float* __restrict__ Uz, const float* __restrict__ h0,
    float* __restrict__ out)
{
    __shared__ __align__(16) float4 hs4[256];                  // staged h/rh: [k][bl]
    __shared__ __align__(16) unsigned long long red[8][32][4]; // warp partials

    const int tid  = threadIdx.x;
    const int w    = tid >> 5;
    const int lane = tid & 31;
    const int bg   = blockIdx.x & (NB - 1);
    const int ng   = blockIdx.x >> 4;
    const int n_g  = ng * NPG + lane;       // this lane's column (compute role)

    // loop-invariant U slices in registers: uX[i] = UX[(w*32+i)*256 + n_g]
    float uz[KPW], ur[KPW], uh[KPW];
#pragma unroll
    for (int i = 0; i < KPW; i++) {
        int k = w * KPW + i;
        uz[i] = __ldg(&Uz[k * DIM + n_g]);
        ur[i] = __ldg(&Ur[k * DIM + n_g]);
        uh[i] = __ldg(&Uh[k * DIM + n_g]);
    }

    const bool owner = (tid < 64);
    const int on  = tid & 31;               // owner's column (local)
    const int obp = tid >> 5;               // owner's batch pair (0 or 1)
    const int n_og = ng * NPG + on;
    const int b0   = bg * BPG + obp * 2;    // owner's first global batch

    float hp0 = 0.f, hp1 = 0.f;             // h pair for (b0, b0+1)
    if (owner) {
        float v = __ldg(&h0[n_og]);         // init broadcast over batch
        hp0 = v; hp1 = v;
        *(float2*)&g_h[(bg * DIM + n_og) * BPG + obp * 2] = make_float2(hp0, hp1);
        __threadfence();
    }
    unsigned bars = 0;
    ROW_BARRIER();

    const float4* gh4  = (const float4*)g_h;    // 256 float4 per bg
    const float4* grh4 = (const float4*)g_rh;

    float zp0, zp1, rp0, rp1;
    float xz0, xz1, xr0, xr1, xh0, xh1;

    for (int t = 0; t < T_STEPS; t++) {
        if (owner) {
            // x projections for this step (DRAM; hidden behind phase 1)
            int base = ((t * NN + ng) * NB + bg) * 128;
            int a0 = base + (obp * 2) * 32 + on;
            xz0 = __ldg(&g_Xz[a0]); xz1 = __ldg(&g_Xz[a0 + 32]);
            xr0 = __ldg(&g_Xr[a0]); xr1 = __ldg(&g_Xr[a0 + 32]);
            xh0 = __ldg(&g_Xh[a0]); xh1 = __ldg(&g_Xh[a0 + 32]);
            // emit PRE-update hidden (reference semantics)
            out[(t * BATCH + b0) * DIM + n_og]     = hp0;
            out[(t * BATCH + b0 + 1) * DIM + n_og] = hp1;
        }

        // ---- phase 1: stage h (4KB, 1 LDG.128/thread), z & r matvecs ----
        hs4[tid] = __ldcg(gh4 + bg * 256 + tid);
        __syncthreads();

        unsigned long long az01 = 0, az23 = 0, ar01 = 0, ar23 = 0;
#pragma unroll
        for (int i = 0; i < KPW; i++) {
            ulonglong2 hk = *(const ulonglong2*)&hs4[w * KPW + i];  // broadcast
            unsigned long long a = pack2(uz[i], uz[i]);
            unsigned long long c = pack2(ur[i], ur[i]);
            ffma2(az01, hk.x, a); ffma2(az23, hk.y, a);
            ffma2(ar01, hk.x, c); ffma2(ar23, hk.y, c);
        }
        red[w][lane][0] = az01; red[w][lane][1] = az23;
        red[w][lane][2] = ar01; red[w][lane][3] = ar23;
        __syncthreads();

        if (owner) {
            unsigned long long saz = 0, sar = 0;
#pragma unroll
            for (int j = 0; j < 8; j++) {
                saz = addf2(saz, red[j][on][obp]);
                sar = addf2(sar, red[j][on][2 + obp]);
            }
            float2 az = unpack2(saz), ar = unpack2(sar);
            zp0 = sigmoidf_(az.x + xz0); zp1 = sigmoidf_(az.y + xz1);
            rp0 = sigmoidf_(ar.x + xr0); rp1 = sigmoidf_(ar.y + xr1);
            *(float2*)&g_rh[(bg * DIM + n_og) * BPG + obp * 2] =
                make_float2(rp0 * hp0, rp1 * hp1);
            __threadfence();
        }
        ROW_BARRIER();

        // ---- phase 2: stage r*h, h_bar matvec, combine, publish h ----
        hs4[tid] = __ldcg(grh4 + bg * 256 + tid);
        __syncthreads();

        unsigned long long ah01 = 0, ah23 = 0;
#pragma unroll
        for (int i = 0; i < KPW; i++) {
            ulonglong2 hk = *(const ulonglong2*)&hs4[w * KPW + i];
            unsigned long long a = pack2(uh[i], uh[i]);
            ffma2(ah01, hk.x, a); ffma2(ah23, hk.y, a);
        }
        red[w][lane][0] = ah01; red[w][lane][1] = ah23;
        __syncthreads();

        if (owner) {
            unsigned long long s = 0;
#pragma unroll
            for (int j = 0; j < 8; j++) s = addf2(s, red[j][on][obp]);
            float2 ah = unpack2(s);
            float hb0 = tanh_clamped(ah.x + xh0);
            float hb1 = tanh_clamped(ah.y + xh1);
            hp0 = (1.0f - rp0) * hp0 + zp0 * hb0;   // (1-r) per reference
            hp1 = (1.0f - rp1) * hp1 + zp1 * hb1;
            *(float2*)&g_h[(bg * DIM + n_og) * BPG + obp * 2] = make_float2(hp0, hp1);
            __threadfence();
        }
        ROW_BARRIER();
    }
}

extern "C" void kernel_launch(void* const* d_in, const int* in_sizes, int n_in,
                              void* d_out, int out_size)
{
    const float* X   = (const float*)d_in[0];
    const float* W   = (const float*)d_in[1];
    const float* U   = (const float*)d_in[2];
    const float* bh  = (const float*)d_in[3];
    const float* W_r = (const float*)d_in[4];
    const float* U_r = (const float*)d_in[5];
    const float* b_r = (const float*)d_in[6];
    const float* W_z = (const float*)d_in[7];
    const float* U_z = (const float*)d_in[8];
    const float* b_z = (const float*)d_in[9];
    const float* h0  = (const float*)d_in[10];
    float* out = (float*)d_out;

    x_proj_kernel<<<dim3(T_STEPS, 4, 3), 256>>>(X, W_z, W_r, W, b_z, b_r, bh);
    gru_rec_kernel<<<NCTA, 256>>>(U, U_r, U_z, h0, out);
}

// round 12
// speedup vs baseline: 5.0554x; 1.3803x over previous
#include <cuda_runtime.h>
#include <math.h>

#define T_STEPS 1024
#define BATCH   64
#define DIM     256
#define NB      16              // batch groups = clusters (independent rows)
#define BPG     4               // batches per group
#define NN      8               // column-group CTAs per cluster
#define NPG     32              // columns per CTA
#define NCTA    (NB * NN)       // 128 CTAs
#define KPW     32              // k-range per warp (8 warps cover DIM=256)
#define TX_BYTES 4096u          // per barrier per phase: 8 CTAs * 64 owners * 8B

// ---- scratch (static __device__ arrays: allocation-free) ----
__device__ float g_Xz[T_STEPS * BATCH * DIM];   // [((t*8+ng)*16+bg)*128 + bl*32 + nl]
__device__ float g_Xr[T_STEPS * BATCH * DIM];
__device__ float g_Xh[T_STEPS * BATCH * DIM];

// ---- packed fp32x2 helpers (PTX-only f32x2 ops: 2x fp32 throughput) ----
__device__ __forceinline__ unsigned long long pack2(float lo, float hi) {
    unsigned long long r;
    asm("mov.b64 %0, {%1, %2};" : "=l"(r) : "f"(lo), "f"(hi));
    return r;
}
__device__ __forceinline__ float2 unpack2(unsigned long long v) {
    float lo, hi;
    asm("mov.b64 {%0, %1}, %2;" : "=f"(lo), "=f"(hi) : "l"(v));
    return make_float2(lo, hi);
}
__device__ __forceinline__ void ffma2(unsigned long long& d,
                                      unsigned long long a, unsigned long long b) {
    asm("fma.rn.f32x2 %0, %1, %2, %0;" : "+l"(d) : "l"(a), "l"(b));
}
__device__ __forceinline__ unsigned long long addf2(unsigned long long a,
                                                    unsigned long long b) {
    unsigned long long r;
    asm("add.rn.f32x2 %0, %1, %2;" : "=l"(r) : "l"(a), "l"(b));
    return r;
}
__device__ __forceinline__ float sigmoidf_(float x) {
    return 1.0f / (1.0f + __expf(-x));
}
__device__ __forceinline__ float tanh_clamped(float x) {
    x = fminf(fmaxf(x, -20.0f), 20.0f);
    float e = __expf(-2.0f * x);
    return (1.0f - e) / (1.0f + e);
}

// ---- cluster / DSMEM primitives ----
__device__ __forceinline__ unsigned smem_u32(const void* p) {
    unsigned a;
    asm("{ .reg .u64 t; cvta.to.shared.u64 t, %1; cvt.u32.u64 %0, t; }"
        : "=r"(a) : "l"(p));
    return a;
}
__device__ __forceinline__ void mbar_init(unsigned mbar, unsigned count) {
    asm volatile("mbarrier.init.shared.b64 [%0], %1;" :: "r"(mbar), "r"(count)
                 : "memory");
}
__device__ __forceinline__ void mbar_expect_tx(unsigned mbar, unsigned bytes) {
    asm volatile("mbarrier.arrive.expect_tx.shared.b64 _, [%0], %1;"
                 :: "r"(mbar), "r"(bytes) : "memory");
}
// Remote 8B store whose completion is signaled (with data-visibility guarantee)
// to the DESTINATION CTA's mbarrier via complete_tx — no fences needed.
__device__ __forceinline__ void dsmem_st_async64(unsigned laddr, unsigned lmbar,
                                                 unsigned rank, unsigned long long v) {
    asm volatile(
        "{ .reg .b32 ra, rm;\n\t"
        "mapa.shared::cluster.u32 ra, %0, %2;\n\t"
        "mapa.shared::cluster.u32 rm, %1, %2;\n\t"
        "st.async.shared::cluster.mbarrier::complete_tx::bytes.b64 [ra], %3, [rm]; }"
        :: "r"(laddr), "r"(lmbar), "r"(rank), "l"(v) : "memory");
}
__device__ __forceinline__ void mbar_wait(unsigned mbar, unsigned parity) {
    unsigned done;
    asm volatile(
        "{ .reg .pred p;\n\t"
        "mbarrier.try_wait.parity.acquire.cta.shared::cta.b64 p, [%1], %2;\n\t"
        "selp.b32 %0, 1, 0, p; }"
        : "=r"(done) : "r"(mbar), "r"(parity) : "memory");
    while (!done) {
        asm volatile(
            "{ .reg .pred p;\n\t"
            "mbarrier.try_wait.parity.acquire.cta.shared::cta.b64 p, [%1], %2, 0x989680;\n\t"
            "selp.b32 %0, 1, 0, p; }"
            : "=r"(done) : "r"(mbar), "r"(parity) : "memory");
    }
}
#define CLUSTER_SYNC_() do {                                        \
    asm volatile("barrier.cluster.arrive.aligned;" ::: "memory");   \
    asm volatile("barrier.cluster.wait.aligned;"   ::: "memory");   \
} while (0)

// ============================================================
// Kernel A: X @ Wg + bg for g in {z, r, h} (fp32, FFMA2).
// Output layout: Xg[((t*8 + n/32)*16 + b/4)*128 + (b%4)*32 + (n%32)]
// ============================================================
__global__ __launch_bounds__(256) void x_proj_kernel(
    const float* __restrict__ X,
    const float* __restrict__ Wz, const float* __restrict__ Wr, const float* __restrict__ Wh,
    const float* __restrict__ bz, const float* __restrict__ br, const float* __restrict__ bh)
{
    const int tid = threadIdx.x;
    const float* W; const float* bias; float* out;
    if (blockIdx.z == 0)      { W = Wz; bias = bz; out = g_Xz; }
    else if (blockIdx.z == 1) { W = Wr; bias = br; out = g_Xr; }
    else                      { W = Wh; bias = bh; out = g_Xh; }

    __shared__ __align__(16) float As[32][68];  // transposed X tile: As[k][row]
    __shared__ __align__(16) float Ws[32][68];  // W tile: Ws[k][col]

    const int tx = tid & 15;          // 4 cols each
    const int ty = tid >> 4;          // 4 rows each (rows = batch)
    const int t = blockIdx.x;
    const int col0 = blockIdx.y * 64;

    unsigned long long acc2[4][2];
#pragma unroll
    for (int i = 0; i < 4; i++) { acc2[i][0] = 0ull; acc2[i][1] = 0ull; }

    for (int kk = 0; kk < DIM; kk += 32) {
#pragma unroll
        for (int li = 0; li < 2; li++) {
            int idx = li * 256 + tid;
            int r = idx >> 3;
            int q = idx & 7;
            float4 v = *(const float4*)&X[(t * 64 + r) * DIM + kk + q * 4];
            As[q * 4 + 0][r] = v.x;
            As[q * 4 + 1][r] = v.y;
            As[q * 4 + 2][r] = v.z;
            As[q * 4 + 3][r] = v.w;
        }
#pragma unroll
        for (int li = 0; li < 2; li++) {
            int idx = li * 256 + tid;
            int k = idx >> 4;
            int q = idx & 15;
            float4 v = *(const float4*)&W[(kk + k) * DIM + col0 + q * 4];
            *(float4*)&Ws[k][q * 4] = v;
        }
        __syncthreads();
#pragma unroll 8
        for (int k = 0; k < 32; k++) {
            float4 a = *(const float4*)&As[k][ty * 4];
            ulonglong2 w2 = *(const ulonglong2*)&Ws[k][tx * 4];
            unsigned long long d0 = pack2(a.x, a.x);
            unsigned long long d1 = pack2(a.y, a.y);
            unsigned long long d2 = pack2(a.z, a.z);
            unsigned long long d3 = pack2(a.w, a.w);
            ffma2(acc2[0][0], d0, w2.x); ffma2(acc2[0][1], d0, w2.y);
            ffma2(acc2[1][0], d1, w2.x); ffma2(acc2[1][1], d1, w2.y);
            ffma2(acc2[2][0], d2, w2.x); ffma2(acc2[2][1], d2, w2.y);
            ffma2(acc2[3][0], d3, w2.x); ffma2(acc2[3][1], d3, w2.y);
        }
        __syncthreads();
    }

    float4 bias4 = __ldg((const float4*)&bias[col0 + tx * 4]);
    const int ngx = blockIdx.y * 2 + (tx >> 3);
    const int nl0 = (tx & 7) * 4;
#pragma unroll
    for (int i = 0; i < 4; i++) {
        float2 p0 = unpack2(acc2[i][0]);
        float2 p1 = unpack2(acc2[i][1]);
        float4 v = make_float4(p0.x + bias4.x, p0.y + bias4.y,
                               p1.x + bias4.z, p1.y + bias4.w);
        *(float4*)&out[((t * NN + ngx) * NB + ty) * 128 + i * 32 + nl0] = v;
    }
}

// ============================================================
// Kernel B: persistent recurrence, 128 CTAs, clusters of 8.
// Cluster = batch group bg (4 batches); rank ng owns 32 columns.
// Exchange via st.async + mbarrier complete_tx: each owner's 8B slice is
// delivered to all 8 peers' hsA/hsB with HW-guaranteed visibility at
// barrier-phase completion. Per phase each CTA issues ONE
// arrive.expect_tx(4096B); consumers wait locally (acquire).
// Self-delivery tx makes red-array and buffer reuse self-gating.
// ============================================================
__global__ __launch_bounds__(256) __cluster_dims__(NN, 1, 1)
void gru_rec_kernel(
    const float* __restrict__ Uh, const float* __restrict__ Ur,
    const float* __restrict__ Uz, const float* __restrict__ h0,
    float* __restrict__ out)
{
    __shared__ __align__(16) float4 hsA[256];                  // h   [k][bl]
    __shared__ __align__(16) float4 hsB[256];                  // r*h [k][bl]
    __shared__ __align__(16) unsigned long long red[8][32][4]; // warp partials
    __shared__ __align__(8)  unsigned long long mbars[2];      // [A, B]

    const int tid  = threadIdx.x;
    const int w    = tid >> 5;
    const int lane = tid & 31;
    const int bg   = blockIdx.x >> 3;           // cluster id = batch group
    const unsigned ng = blockIdx.x & (NN - 1);  // rank in cluster
    const int n_g  = (int)ng * NPG + lane;      // compute-role column

    const unsigned hsA_a = smem_u32(hsA);
    const unsigned hsB_a = smem_u32(hsB);
    const unsigned mA = smem_u32(&mbars[0]);
    const unsigned mB = smem_u32(&mbars[1]);

    // loop-invariant U slices in registers
    float uz[KPW], ur[KPW], uh[KPW];
#pragma unroll
    for (int i = 0; i < KPW; i++) {
        int k = w * KPW + i;
        uz[i] = __ldg(&Uz[k * DIM + n_g]);
        ur[i] = __ldg(&Ur[k * DIM + n_g]);
        uh[i] = __ldg(&Uh[k * DIM + n_g]);
    }

    if (tid == 0) { mbar_init(mA, 1); mbar_init(mB, 1); }
    __syncthreads();
    CLUSTER_SYNC_();                    // barriers visible before any st.async

    const bool owner = (tid < 64);
    const int on   = tid & 31;          // owner column (local)
    const int obp  = tid >> 5;          // owner batch pair (0/1)
    const int n_og = (int)ng * NPG + on;
    const int b0   = bg * BPG + obp * 2;
    // byte offset of this owner's float2 inside hsA/hsB: [k=n_og][bl=obp*2]
    const unsigned push_off = (unsigned)(n_og * 16 + obp * 8);

    // credits for the first fill of each buffer (phase 0)
    if (tid == 0) { mbar_expect_tx(mA, TX_BYTES); mbar_expect_tx(mB, TX_BYTES); }

    float hp0 = 0.f, hp1 = 0.f;
    if (owner) {
        float v = __ldg(&h0[n_og]);     // init hidden, broadcast over batch
        hp0 = v; hp1 = v;
        unsigned long long pv = pack2(hp0, hp1);
#pragma unroll
        for (unsigned p = 0; p < NN; p++)
            dsmem_st_async64(hsA_a + push_off, mA, p, pv);
    }

    float zp0, zp1, rp0, rp1;
    float xz0, xz1, xr0, xr1, xh0, xh1;

    for (int t = 0; t < T_STEPS; t++) {
        const unsigned par = (unsigned)(t & 1);

        if (owner) {
            // x projections for this step (independent of h; overlaps wait)
            int a0 = ((t * NN + (int)ng) * NB + bg) * 128 + (obp * 2) * 32 + on;
            xz0 = __ldg(&g_Xz[a0]); xz1 = __ldg(&g_Xz[a0 + 32]);
            xr0 = __ldg(&g_Xr[a0]); xr1 = __ldg(&g_Xr[a0 + 32]);
            xh0 = __ldg(&g_Xh[a0]); xh1 = __ldg(&g_Xh[a0 + 32]);
            // emit PRE-update hidden (reference semantics)
            out[(t * BATCH + b0) * DIM + n_og]     = hp0;
            out[(t * BATCH + b0 + 1) * DIM + n_og] = hp1;
        }

        // ---- phase 1: wait for h(t), z & r matvecs ----
        mbar_wait(mA, par);
        if (tid == 0 && t + 1 < T_STEPS) mbar_expect_tx(mA, TX_BYTES);

        unsigned long long az01 = 0, az23 = 0, ar01 = 0, ar23 = 0;
#pragma unroll
        for (int i = 0; i < KPW; i++) {
            ulonglong2 hk = *(const ulonglong2*)&hsA[w * KPW + i];  // broadcast
            unsigned long long a = pack2(uz[i], uz[i]);
            unsigned long long c = pack2(ur[i], ur[i]);
            ffma2(az01, hk.x, a); ffma2(az23, hk.y, a);
            ffma2(ar01, hk.x, c); ffma2(ar23, hk.y, c);
        }
        red[w][lane][0] = az01; red[w][lane][1] = az23;
        red[w][lane][2] = ar01; red[w][lane][3] = ar23;
        __syncthreads();

        if (owner) {
            unsigned long long saz = 0, sar = 0;
#pragma unroll
            for (int j = 0; j < 8; j++) {
                saz = addf2(saz, red[j][on][obp]);
                sar = addf2(sar, red[j][on][2 + obp]);
            }
            float2 az = unpack2(saz), ar = unpack2(sar);
            zp0 = sigmoidf_(az.x + xz0); zp1 = sigmoidf_(az.y + xz1);
            rp0 = sigmoidf_(ar.x + xr0); rp1 = sigmoidf_(ar.y + xr1);
            unsigned long long pv = pack2(rp0 * hp0, rp1 * hp1);
#pragma unroll
            for (unsigned p = 0; p < NN; p++)
                dsmem_st_async64(hsB_a + push_off, mB, p, pv);
        }

        // ---- phase 2: wait for r*h(t), h_bar matvec, combine, publish h ----
        // (wait passes only after ALL CTAs' owners pushed -> own owners are
        //  past their red[] reads, so phase-2 red writes below are safe)
        mbar_wait(mB, par);
        if (tid == 0 && t + 1 < T_STEPS) mbar_expect_tx(mB, TX_BYTES);

        unsigned long long ah01 = 0, ah23 = 0;
#pragma unroll
        for (int i = 0; i < KPW; i++) {
            ulonglong2 hk = *(const ulonglong2*)&hsB[w * KPW + i];
            unsigned long long a = pack2(uh[i], uh[i]);
            ffma2(ah01, hk.x, a); ffma2(ah23, hk.y, a);
        }
        red[w][lane][0] = ah01; red[w][lane][1] = ah23;
        __syncthreads();

        if (owner) {
            unsigned long long s = 0;
#pragma unroll
            for (int j = 0; j < 8; j++) s = addf2(s, red[j][on][obp]);
            float2 ah = unpack2(s);
            float hb0 = tanh_clamped(ah.x + xh0);
            float hb1 = tanh_clamped(ah.y + xh1);
            hp0 = (1.0f - rp0) * hp0 + zp0 * hb0;   // (1-r) per reference
            hp1 = (1.0f - rp1) * hp1 + zp1 * hb1;
            if (t + 1 < T_STEPS) {                  // no in-flight ops at exit
                unsigned long long pv = pack2(hp0, hp1);
#pragma unroll
                for (unsigned p = 0; p < NN; p++)
                    dsmem_st_async64(hsA_a + push_off, mA, p, pv);
            }
        }
    }

    CLUSTER_SYNC_();    // no CTA exits while peers might still touch its smem
}

extern "C" void kernel_launch(void* const* d_in, const int* in_sizes, int n_in,
                              void* d_out, int out_size)
{
    const float* X   = (const float*)d_in[0];
    const float* W   = (const float*)d_in[1];
    const float* U   = (const float*)d_in[2];
    const float* bh  = (const float*)d_in[3];
    const float* W_r = (const float*)d_in[4];
    const float* U_r = (const float*)d_in[5];
    const float* b_r = (const float*)d_in[6];
    const float* W_z = (const float*)d_in[7];
    const float* U_z = (const float*)d_in[8];
    const float* b_z = (const float*)d_in[9];
    const float* h0  = (const float*)d_in[10];
    float* out = (float*)d_out;

    x_proj_kernel<<<dim3(T_STEPS, 4, 3), 256>>>(X, W_z, W_r, W, b_z, b_r, bh);
    gru_rec_kernel<<<NCTA, 256>>>(U, U_r, U_z, h0, out);
}